// round 3
// baseline (speedup 1.0000x reference)
#include <cuda_runtime.h>
#include <cuda_bf16.h>
#include <cstdint>

// MixedEmbeddingV2: out[b,s,:] = emb_weight[x[b,s], :] * col_scale[:]
// col_scale is a 4-segment step function (segments of 192 columns):
//   seg0: w0+w1+w2+w3, seg1: w1+w2+w3, seg2: w2+w3, seg3: w3
//
// x arrives as int32 (JAX x64-disabled downcasts the declared int64).
// HBM-bound gather+scale stream: ~50 MB read + ~50 MB write.
// 8 tokens per CTA, 192 threads, one float4 per thread per token.
// Token ids staged in smem; 8 independent LDG.128 gathers in flight (MLP=8).

#define MAX_D        768
#define VEC_PER_ROW  (MAX_D / 4)   // 192 float4s per row
#define TOK_PER_CTA  8
#define VOCAB        50257

__global__ __launch_bounds__(VEC_PER_ROW)
void mixed_embedding_kernel(const int* __restrict__ x,
                            const float* __restrict__ weights,
                            const float4* __restrict__ emb,   // [VOCAB, 192] float4
                            float4* __restrict__ out,         // [N_TOK, 192] float4
                            int n_tok)
{
    __shared__ int rows_s[TOK_PER_CTA];

    const int tid  = threadIdx.x;                 // 0..191
    const int base = blockIdx.x * TOK_PER_CTA;    // first token of this CTA

    // Stage the 8 token ids once per CTA (clamped: crash-proof even on bad data).
    if (tid < TOK_PER_CTA) {
        int t = base + tid;
        int id = (t < n_tok) ? x[t] : 0;
        id = (id < 0) ? 0 : ((id >= VOCAB) ? VOCAB - 1 : id);
        rows_s[tid] = id;
    }

    // Per-thread column scale: 4-segment suffix sums of weights.
    const float w0 = __ldg(weights + 0);
    const float w1 = __ldg(weights + 1);
    const float w2 = __ldg(weights + 2);
    const float w3 = __ldg(weights + 3);
    const float s3 = w3;
    const float s2 = w2 + s3;
    const float s1 = w1 + s2;
    const float s0 = w0 + s1;
    const int seg = tid / 48;                     // 48 float4s per 192-col segment
    const float scale = (seg == 0) ? s0 : (seg == 1) ? s1 : (seg == 2) ? s2 : s3;

    __syncthreads();

    // Pull ids to registers, then issue 8 independent gathers (front-batched).
    int rows[TOK_PER_CTA];
#pragma unroll
    for (int t = 0; t < TOK_PER_CTA; t++) rows[t] = rows_s[t];

    float4 v[TOK_PER_CTA];
#pragma unroll
    for (int t = 0; t < TOK_PER_CTA; t++)
        v[t] = __ldg(emb + (size_t)rows[t] * VEC_PER_ROW + tid);

#pragma unroll
    for (int t = 0; t < TOK_PER_CTA; t++) {
        float4 r;
        r.x = v[t].x * scale;
        r.y = v[t].y * scale;
        r.z = v[t].z * scale;
        r.w = v[t].w * scale;
        int tok = base + t;
        if (tok < n_tok)
            out[(size_t)tok * VEC_PER_ROW + tid] = r;
    }
}

extern "C" void kernel_launch(void* const* d_in, const int* in_sizes, int n_in,
                              void* d_out, int out_size)
{
    // metadata order: x (int32, B*S), weights (f32, 4), emb_weight (f32, VOCAB*768)
    const int* x         = (const int*)d_in[0];
    const float* weights = (const float*)d_in[1];
    const float4* emb    = (const float4*)d_in[2];
    float4* out          = (float4*)d_out;

    const int n_tok = in_sizes[0];                        // 8 * 2048 = 16384
    const int grid  = (n_tok + TOK_PER_CTA - 1) / TOK_PER_CTA;  // 2048

    mixed_embedding_kernel<<<grid, VEC_PER_ROW>>>(x, weights, emb, out, n_tok);
}